// round 3
// baseline (speedup 1.0000x reference)
#include <cuda_runtime.h>
#include <cstdint>

#define NTOT 500000
#define TM 64
#define THREADS 512
#define NTILES ((NTOT + TM - 1) / TM)

// smem layout (float offsets). All tiles stride-128, XOR-swizzled (no padding).
#define OFF_WT 0
#define OFF_WG 16384
#define OFF_X  32768
#define OFF_M  40960
#define OFF_Y  49152
#define OFF_BT 57344
#define OFF_BG 57472
#define SMEM_FLOATS 57600
#define SMEM_BYTES (SMEM_FLOATS * 4)   // 230400 B <= 232448 (227 KB)

__device__ __forceinline__ uint32_t cvt_tf32_u(float x) {
    uint32_t u;
    asm("cvt.rna.tf32.f32 %0, %1;" : "=r"(u) : "f"(x));
    return u;
}
__device__ __forceinline__ float cvt_tf32_f(float x) {
    return __uint_as_float(cvt_tf32_u(x));
}

__device__ __forceinline__ void mma8(float* c,
                                     uint32_t a0, uint32_t a1, uint32_t a2, uint32_t a3,
                                     uint32_t b0, uint32_t b1) {
    asm volatile(
        "mma.sync.aligned.m16n8k8.row.col.f32.tf32.tf32.f32 "
        "{%0,%1,%2,%3}, {%4,%5,%6,%7}, {%8,%9}, {%0,%1,%2,%3};"
        : "+f"(c[0]), "+f"(c[1]), "+f"(c[2]), "+f"(c[3])
        : "r"(a0), "r"(a1), "r"(a2), "r"(a3), "r"(b0), "r"(b1));
}

__device__ __forceinline__ void cp16(uint32_t saddr, const void* g, int szbytes) {
    asm volatile("cp.async.cg.shared.global [%0], [%1], 16, %2;"
                 :: "r"(saddr), "l"(g), "r"(szbytes));
}
#define CP_COMMIT() asm volatile("cp.async.commit_group;")
#define CP_WAIT(n)  asm volatile("cp.async.wait_group %0;" :: "n"(n))

extern "C" __global__ void zero_out_kernel(float* __restrict__ out) {
    int i = blockIdx.x * blockDim.x + threadIdx.x;
    if (i < 128 * 128) out[i] = 0.0f;
}

extern "C" __global__ void __launch_bounds__(THREADS, 1)
agg_kernel(const float* __restrict__ nodes, const int* __restrict__ masks,
           const float* __restrict__ Wt, const float* __restrict__ bt,
           const float* __restrict__ Wg, const float* __restrict__ bg,
           float* __restrict__ out) {
    extern __shared__ float sm[];
    float* sWt = sm + OFF_WT;
    float* sWg = sm + OFF_WG;
    float* sX  = sm + OFF_X;
    int*   sM  = (int*)(sm + OFF_M);
    float* sY  = sm + OFF_Y;
    float* sBt = sm + OFF_BT;
    float* sBg = sm + OFF_BG;

    const uint32_t smem_u32 = (uint32_t)__cvta_generic_to_shared(sm);
    const uint32_t sx_u32 = smem_u32 + OFF_X * 4;
    const uint32_t sm_u32 = smem_u32 + OFF_M * 4;

    const int tid  = threadIdx.x;
    const int warp = tid >> 5;
    const int lane = tid & 31;
    const int tg   = lane & 3;   // k/col selector within quad
    const int gid  = lane >> 2;  // row selector

    // W + bias load (once). Pre-round W to tf32 (rna), store XOR-swizzled:
    // w_idx(k,n) = k*128 + (n ^ ((k&3)<<3))
    for (int i = tid; i < 128 * 128; i += THREADS) {
        int k = i >> 7, n = i & 127;
        int idx = (k << 7) + (n ^ ((k & 3) << 3));
        sWt[idx] = cvt_tf32_f(Wt[i]);
        sWg[idx] = cvt_tf32_f(Wg[i]);
    }
    if (tid < 128) { sBt[tid] = bt[tid]; sBg[tid] = bg[tid]; }

    // Phase A warp mapping
    const int wm = warp & 3;          // node-row tile: rows [16*wm, +16)
    const int wq = warp >> 2;         // col group: cols [32*wq, +32)
    // Phase B warp mapping
    const int pm = warp & 7;          // batch-row tile
    const int ph = warp >> 3;         // d-col half

    // Pooling accumulators live in registers across all tiles
    float pc[8][4];
#pragma unroll
    for (int j = 0; j < 8; j++)
#pragma unroll
        for (int r = 0; r < 4; r++) pc[j][r] = 0.0f;

    const int stride = gridDim.x;
    int t = blockIdx.x;

    // ---- prologue: start X(t0) streaming ----
    if (t < NTILES) {
        const int n0 = t * TM;
#pragma unroll
        for (int p = 0; p < 4; p++) {
            int id = tid + THREADS * p;
            int row = id >> 5, ch = id & 31;
            int n = n0 + row;
            const float* g = nodes + (size_t)(n < NTOT ? n : 0) * 128 + ch * 4;
            uint32_t sa = sx_u32 + (((row << 7) + ((ch ^ (row & 7)) << 2)) << 2);
            cp16(sa, g, n < NTOT ? 16 : 0);
        }
    }
    CP_COMMIT();

    for (; t < NTILES; t += stride) {
        const int n0 = t * TM;

        CP_WAIT(0);          // X(t) landed
        __syncthreads();     // all warps past phase B(t-1); X(t) visible

        // ---- start mask(t) streaming (overlaps all of phase A) ----
#pragma unroll
        for (int p = 0; p < 4; p++) {
            int id = tid + THREADS * p;
            int b = id >> 4, ch = id & 15;
            int n = n0 + ch * 4;
            const int* g = masks + (size_t)b * NTOT + (n < NTOT ? n : 0);
            uint32_t sa = sm_u32 + ((((b << 6) + ((ch ^ (b & 7)) << 2))) << 2);
            cp16(sa, g, n < NTOT ? 16 : 0);
        }
        CP_COMMIT();

        // ---- Phase A: [64x128] @ [128x128] x2, single tf32 pass each ----
        float accD[4][4], accG[4][4];
#pragma unroll
        for (int j = 0; j < 4; j++)
#pragma unroll
            for (int r = 0; r < 4; r++) { accD[j][r] = 0.0f; accG[j][r] = 0.0f; }

        const int mrow  = wm * 16 + gid;
        const int ncol0 = 32 * wq + gid;
        const int xsw   = gid << 2;       // X swizzle ((row&7)<<2), rows mrow/mrow+8 share it
        const int wsw   = tg << 3;        // W/Y swizzle ((k&3)<<3), k0 and k0+4 share it

#pragma unroll 4
        for (int ks = 0; ks < 16; ks++) {
            const int k0 = ks * 8 + tg;
            uint32_t a0 = cvt_tf32_u(sX[(mrow << 7)       + (k0 ^ xsw)]);
            uint32_t a1 = cvt_tf32_u(sX[((mrow + 8) << 7) + (k0 ^ xsw)]);
            uint32_t a2 = cvt_tf32_u(sX[(mrow << 7)       + ((k0 + 4) ^ xsw)]);
            uint32_t a3 = cvt_tf32_u(sX[((mrow + 8) << 7) + ((k0 + 4) ^ xsw)]);
            const int base0 = k0 << 7;
            const int base1 = (k0 + 4) << 7;
#pragma unroll
            for (int j = 0; j < 4; j++) {
                const int cidx = (ncol0 + 8 * j) ^ wsw;
                uint32_t d0 = __float_as_uint(sWt[base0 + cidx]);
                uint32_t d1 = __float_as_uint(sWt[base1 + cidx]);
                mma8(accD[j], a0, a1, a2, a3, d0, d1);
                uint32_t g0 = __float_as_uint(sWg[base0 + cidx]);
                uint32_t g1 = __float_as_uint(sWg[base1 + cidx]);
                mma8(accG[j], a0, a1, a2, a3, g0, g1);
            }
        }
        __syncthreads();   // phase A done reading sX

        // ---- start X(t+stride) streaming (overlaps epilogue + phase B) ----
        {
            const int tn = t + stride;
            if (tn < NTILES) {
                const int nn0 = tn * TM;
#pragma unroll
                for (int p = 0; p < 4; p++) {
                    int id = tid + THREADS * p;
                    int row = id >> 5, ch = id & 31;
                    int n = nn0 + row;
                    const float* g = nodes + (size_t)(n < NTOT ? n : 0) * 128 + ch * 4;
                    uint32_t sa = sx_u32 + (((row << 7) + ((ch ^ (row & 7)) << 2)) << 2);
                    cp16(sa, g, n < NTOT ? 16 : 0);
                }
            }
            CP_COMMIT();
        }

        // ---- Epilogue: y = (d + bt) * sigmoid(g + bg), tf32-rounded into sY ----
#pragma unroll
        for (int j = 0; j < 4; j++) {
#pragma unroll
            for (int r = 0; r < 4; r++) {
                int col = 32 * wq + 8 * j + 2 * tg + (r & 1);
                int row = wm * 16 + gid + ((r >> 1) ? 8 : 0);
                float d  = accD[j][r] + sBt[col];
                float gl = accG[j][r] + sBg[col];
                float gate = 1.0f / (1.0f + __expf(-gl));
                sY[(row << 7) + (col ^ ((row & 3) << 3))] = cvt_tf32_f(d * gate);
            }
        }

        CP_WAIT(1);        // mask(t) landed (X(t+1) may still be in flight)
        __syncthreads();   // Y + mask visible to all

        // ---- Phase B: pool += M[128x64] @ Y[64x128] ----
        const int brow = pm * 16 + gid;
        const int msw  = gid << 2;   // mask swizzle ((b&7)<<2), brow/brow+8 share it
#pragma unroll 4
        for (int ks = 0; ks < 8; ks++) {
            const int kk = ks * 8 + tg;
            uint32_t m0 = __float_as_uint((float)sM[(brow << 6)       + (kk ^ msw)]);
            uint32_t m1 = __float_as_uint((float)sM[((brow + 8) << 6) + (kk ^ msw)]);
            uint32_t m2 = __float_as_uint((float)sM[(brow << 6)       + ((kk + 4) ^ msw)]);
            uint32_t m3 = __float_as_uint((float)sM[((brow + 8) << 6) + ((kk + 4) ^ msw)]);
            const int yb0 = kk << 7;
            const int yb1 = (kk + 4) << 7;
#pragma unroll
            for (int j = 0; j < 8; j++) {
                const int cidx = (64 * ph + 8 * j + gid) ^ wsw;
                uint32_t y0 = __float_as_uint(sY[yb0 + cidx]);
                uint32_t y1 = __float_as_uint(sY[yb1 + cidx]);
                mma8(pc[j], m0, m1, m2, m3, y0, y1);
            }
        }
    }

    // ---- Final reduction: one atomicAdd per pooled element per CTA ----
#pragma unroll
    for (int j = 0; j < 8; j++) {
#pragma unroll
        for (int r = 0; r < 4; r++) {
            int b = pm * 16 + gid + ((r >> 1) ? 8 : 0);
            int c = 64 * ph + 8 * j + 2 * tg + (r & 1);
            atomicAdd(&out[b * 128 + c], pc[j][r]);
        }
    }
}

extern "C" void kernel_launch(void* const* d_in, const int* in_sizes, int n_in,
                              void* d_out, int out_size) {
    (void)in_sizes; (void)n_in; (void)out_size;
    const float* nodes = (const float*)d_in[0];
    const int*   masks = (const int*)d_in[1];
    const float* Wt    = (const float*)d_in[2];
    const float* bt    = (const float*)d_in[3];
    const float* Wg    = (const float*)d_in[4];
    const float* bg    = (const float*)d_in[5];
    float* out = (float*)d_out;

    cudaFuncSetAttribute(agg_kernel, cudaFuncAttributeMaxDynamicSharedMemorySize, SMEM_BYTES);

    zero_out_kernel<<<32, 512>>>(out);
    agg_kernel<<<148, THREADS, SMEM_BYTES>>>(nodes, masks, Wt, bt, Wg, bg, out);
}

// round 5
// speedup vs baseline: 1.7309x; 1.7309x over previous
#include <cuda_runtime.h>
#include <cstdint>

#define NTOT 500000
#define CT 64
#define THREADS 512
#define NTILES ((NTOT + CT - 1) / CT)   // 7813

// smem layout (float offsets)
#define OFF_WT 0        // [128 k][128 n], n ^ ((k&3)<<3)
#define OFF_WG 16384
#define OFF_X  32768    // [64 m][128 k], k ^ ((m&7)<<2)
#define OFF_M  40960    // [128 b][64 k] int, k ^ ((b&7)<<2)
#define OFF_Y  49152    // [64 m][128 n], n ^ (((m&3)<<3)|((m&4)>>2))
#define SMEM_FLOATS 57344
#define SMEM_BYTES (SMEM_FLOATS * 4)    // 229376 <= 232448

__device__ __forceinline__ float cvt_tf32_f(float x) {
    uint32_t u; asm("cvt.rna.tf32.f32 %0, %1;" : "=r"(u) : "f"(x));
    return __uint_as_float(u);
}
__device__ __forceinline__ void mma8(float* c,
                                     uint32_t a0, uint32_t a1, uint32_t a2, uint32_t a3,
                                     uint32_t b0, uint32_t b1) {
    asm volatile(
        "mma.sync.aligned.m16n8k8.row.col.f32.tf32.tf32.f32 "
        "{%0,%1,%2,%3}, {%4,%5,%6,%7}, {%8,%9}, {%0,%1,%2,%3};"
        : "+f"(c[0]), "+f"(c[1]), "+f"(c[2]), "+f"(c[3])
        : "r"(a0), "r"(a1), "r"(a2), "r"(a3), "r"(b0), "r"(b1));
}
__device__ __forceinline__ void cp16(uint32_t saddr, const void* g, int szbytes) {
    asm volatile("cp.async.cg.shared.global [%0], [%1], 16, %2;"
                 :: "r"(saddr), "l"(g), "r"(szbytes));
}
#define CP_COMMIT() asm volatile("cp.async.commit_group;")
#define CP_WAIT(n)  asm volatile("cp.async.wait_group %0;" :: "n"(n))

extern "C" __global__ void zero_out_kernel(float* __restrict__ out) {
    int i = blockIdx.x * blockDim.x + threadIdx.x;
    if (i < 128 * 128) out[i] = 0.0f;
}

extern "C" __global__ void __launch_bounds__(THREADS, 1)
agg_kernel(const float* __restrict__ nodes, const int* __restrict__ masks,
           const float* __restrict__ Wt, const float* __restrict__ bt,
           const float* __restrict__ Wg, const float* __restrict__ bg,
           float* __restrict__ out) {
    extern __shared__ float sm[];
    float* sWt = sm + OFF_WT;
    float* sWg = sm + OFF_WG;
    float* sX  = sm + OFF_X;
    int*   sM  = (int*)(sm + OFF_M);
    float* sY  = sm + OFF_Y;

    const uint32_t smem_u32 = (uint32_t)__cvta_generic_to_shared(sm);
    const uint32_t sx_u32 = smem_u32 + OFF_X * 4;
    const uint32_t sm_u32 = smem_u32 + OFF_M * 4;

    const int tid  = threadIdx.x;
    const int warp = tid >> 5;
    const int lane = tid & 31;
    const int tg   = lane & 3;
    const int gid  = lane >> 2;

    // ---- W + bias once; W pre-rounded rna ----
    for (int i = tid; i < 128 * 128; i += THREADS) {
        int k = i >> 7, n = i & 127;
        int idx = (k << 7) + (n ^ ((k & 3) << 3));
        sWt[idx] = cvt_tf32_f(Wt[i]);
        sWg[idx] = cvt_tf32_f(Wg[i]);
    }

    // Phase A mapping: 32m x 16n (both matrices per warp)
    const int wm = warp & 1;           // m-base 32*wm
    const int wq = warp >> 1;          // n-base 16*wq (0..112)
    const int mbase = wm << 5;
    const int nb = wq << 4;
    // Phase B mapping: 32b x 32d
    const int pb = warp & 3;           // b-base 32*pb
    const int pd = warp >> 2;          // d-base 32*pd

    // per-thread bias for its 4 output columns (j in {0,1}, r1 in {0,1})
    float btv[2][2], bgv[2][2];
#pragma unroll
    for (int j = 0; j < 2; j++)
#pragma unroll
        for (int r1 = 0; r1 < 2; r1++) {
            int n = nb + 8 * j + 2 * tg + r1;
            btv[j][r1] = bt[n];
            bgv[j][r1] = bg[n];
        }

    // pooling accumulators (persist across tiles): [b-sub][j][4]
    float pc[2][4][4];
#pragma unroll
    for (int s = 0; s < 2; s++)
#pragma unroll
        for (int j = 0; j < 4; j++)
#pragma unroll
            for (int r = 0; r < 4; r++) pc[s][j][r] = 0.0f;

    const int stride = gridDim.x;
    int t = blockIdx.x;

    // ---- prologue: X(t0) ----
    if (t < NTILES) {
        const int n0 = t * CT;
#pragma unroll
        for (int p = 0; p < 4; p++) {
            int id = tid + THREADS * p;             // 0..2047
            int row = id >> 5, ch = id & 31;
            int n = n0 + row;
            const float* g = nodes + (size_t)(n < NTOT ? n : 0) * 128 + ch * 4;
            uint32_t sa = sx_u32 + (((row << 7) + ((ch ^ (row & 7)) << 2)) << 2);
            cp16(sa, g, n < NTOT ? 16 : 0);
        }
    }
    CP_COMMIT();

    const int xsw = gid << 2;          // X row swizzle (rows ≡ gid mod 8)
    const int msw = gid << 2;          // mask row swizzle
    const int swc = ((gid & 3) << 3) | ((gid & 4) >> 2);  // Y write swizzle

    for (; t < NTILES; t += stride) {
        const int n0 = t * CT;
        CP_WAIT(0);
        __syncthreads();

        // ---- stream mask(t) [128 b][64 k] ----
#pragma unroll
        for (int p = 0; p < 4; p++) {
            int id = tid + THREADS * p;
            int b = id >> 4, ch = id & 15;
            int ok = (n0 + ch * 4) < NTOT;
            const int* g = masks + (size_t)b * NTOT + (ok ? n0 + ch * 4 : 0);
            uint32_t sa = sm_u32 + (((b << 6) + ((ch ^ (b & 7)) << 2)) << 2);
            cp16(sa, g, ok ? 16 : 0);
        }
        CP_COMMIT();

        // ---- Phase A: [64m x 128k] @ W[128k x 128n] x2 ----
        float aD[2][2][4], aG[2][2][4];
#pragma unroll
        for (int s = 0; s < 2; s++)
#pragma unroll
            for (int j = 0; j < 2; j++)
#pragma unroll
                for (int r = 0; r < 4; r++) { aD[s][j][r] = 0.0f; aG[s][j][r] = 0.0f; }

#pragma unroll 2
        for (int ks = 0; ks < 16; ks++) {
            const int k0 = ks * 8 + tg;
            const int r0 = (mbase + gid) << 7;
            uint32_t a0 = __float_as_uint(sX[r0 + (k0 ^ xsw)]);
            uint32_t a1 = __float_as_uint(sX[r0 + (8 << 7) + (k0 ^ xsw)]);
            uint32_t a2 = __float_as_uint(sX[r0 + ((k0 + 4) ^ xsw)]);
            uint32_t a3 = __float_as_uint(sX[r0 + (8 << 7) + ((k0 + 4) ^ xsw)]);
            uint32_t a4 = __float_as_uint(sX[r0 + (16 << 7) + (k0 ^ xsw)]);
            uint32_t a5 = __float_as_uint(sX[r0 + (24 << 7) + (k0 ^ xsw)]);
            uint32_t a6 = __float_as_uint(sX[r0 + (16 << 7) + ((k0 + 4) ^ xsw)]);
            uint32_t a7 = __float_as_uint(sX[r0 + (24 << 7) + ((k0 + 4) ^ xsw)]);
            const int base0 = k0 << 7;
            const int base1 = (k0 + 4) << 7;
#pragma unroll
            for (int j = 0; j < 2; j++) {
                const int cidx = (nb + 8 * j + gid) ^ (tg << 3);
                uint32_t d0 = __float_as_uint(sWt[base0 + cidx]);
                uint32_t d1 = __float_as_uint(sWt[base1 + cidx]);
                mma8(aD[0][j], a0, a1, a2, a3, d0, d1);
                mma8(aD[1][j], a4, a5, a6, a7, d0, d1);
                uint32_t g0 = __float_as_uint(sWg[base0 + cidx]);
                uint32_t g1 = __float_as_uint(sWg[base1 + cidx]);
                mma8(aG[0][j], a0, a1, a2, a3, g0, g1);
                mma8(aG[1][j], a4, a5, a6, a7, g0, g1);
            }
        }
        __syncthreads();   // phase A done reading sX

        // ---- prefetch X(t+stride) ----
        {
            const int tn = t + stride;
            if (tn < NTILES) {
                const int nn0 = tn * CT;
#pragma unroll
                for (int p = 0; p < 4; p++) {
                    int id = tid + THREADS * p;
                    int row = id >> 5, ch = id & 31;
                    int n = nn0 + row;
                    const float* g = nodes + (size_t)(n < NTOT ? n : 0) * 128 + ch * 4;
                    uint32_t sa = sx_u32 + (((row << 7) + ((ch ^ (row & 7)) << 2)) << 2);
                    cp16(sa, g, n < NTOT ? 16 : 0);
                }
            }
            CP_COMMIT();
        }

        // ---- epilogue: y = (d+bt)*sigmoid(g+bg), tf32-rounded -> sY ----
#pragma unroll
        for (int s = 0; s < 2; s++)
#pragma unroll
            for (int j = 0; j < 2; j++)
#pragma unroll
                for (int r = 0; r < 4; r++) {
                    int r1 = r & 1, r2 = r >> 1;
                    int m = mbase + 16 * s + 8 * r2 + gid;
                    int n = nb + 8 * j + 2 * tg + r1;
                    float d  = aD[s][j][r] + btv[j][r1];
                    float gl = aG[s][j][r] + bgv[j][r1];
                    float y = d / (1.0f + __expf(-gl));
                    sY[(m << 7) + (n ^ swc)] = cvt_tf32_f(y);
                }

        CP_WAIT(1);        // mask(t) landed
        __syncthreads();   // sY + sM visible

        // ---- Phase B: pool += mask[128b x 64k] @ Y[64k x 128d] ----
        const int brow0 = (pb << 5) + gid;
#pragma unroll 4
        for (int ks = 0; ks < 8; ks++) {
            const int kk = ks * 8 + tg;
            uint32_t m0 = __float_as_uint((float)sM[(brow0 << 6)        + (kk ^ msw)]);
            uint32_t m1 = __float_as_uint((float)sM[((brow0 + 8) << 6)  + (kk ^ msw)]);
            uint32_t m2 = __float_as_uint((float)sM[(brow0 << 6)        + ((kk + 4) ^ msw)]);
            uint32_t m3 = __float_as_uint((float)sM[((brow0 + 8) << 6)  + ((kk + 4) ^ msw)]);
            uint32_t m4 = __float_as_uint((float)sM[((brow0 + 16) << 6) + (kk ^ msw)]);
            uint32_t m5 = __float_as_uint((float)sM[((brow0 + 24) << 6) + (kk ^ msw)]);
            uint32_t m6 = __float_as_uint((float)sM[((brow0 + 16) << 6) + ((kk + 4) ^ msw)]);
            uint32_t m7 = __float_as_uint((float)sM[((brow0 + 24) << 6) + ((kk + 4) ^ msw)]);
            const int yb0 = kk << 7;
            const int yb1 = (kk + 4) << 7;
            const int ysw0 = tg << 3;
            const int ysw1 = (tg << 3) | 1;
#pragma unroll
            for (int j = 0; j < 4; j++) {
                const int d = (pd << 5) + 8 * j + gid;
                uint32_t y0 = __float_as_uint(sY[yb0 + (d ^ ysw0)]);
                uint32_t y1 = __float_as_uint(sY[yb1 + (d ^ ysw1)]);
                mma8(pc[0][j], m0, m1, m2, m3, y0, y1);
                mma8(pc[1][j], m4, m5, m6, m7, y0, y1);
            }
        }
    }

    // ---- final: one atomicAdd per pooled element per CTA ----
    CP_WAIT(0);
#pragma unroll
    for (int s = 0; s < 2; s++)
#pragma unroll
        for (int j = 0; j < 4; j++)
#pragma unroll
            for (int r = 0; r < 4; r++) {
                int b = (pb << 5) + 16 * s + 8 * (r >> 1) + gid;
                int c = (pd << 5) + 8 * j + 2 * tg + (r & 1);
                atomicAdd(&out[b * 128 + c], pc[s][j][r]);
            }
}

extern "C" void kernel_launch(void* const* d_in, const int* in_sizes, int n_in,
                              void* d_out, int out_size) {
    (void)in_sizes; (void)n_in; (void)out_size;
    cudaFuncSetAttribute(agg_kernel, cudaFuncAttributeMaxDynamicSharedMemorySize, SMEM_BYTES);
    zero_out_kernel<<<32, 512>>>((float*)d_out);
    agg_kernel<<<148, THREADS, SMEM_BYTES>>>(
        (const float*)d_in[0], (const int*)d_in[1], (const float*)d_in[2],
        (const float*)d_in[3], (const float*)d_in[4], (const float*)d_in[5], (float*)d_out);
}